// round 7
// baseline (speedup 1.0000x reference)
#include <cuda_runtime.h>

#define FULL_MASK 0xFFFFFFFFu

constexpr int H = 512;
constexpr int W = 512;
constexpr int NPLANE = 8 * 16;         // 128 independent planes
constexpr int CPL = 4;                 // columns per lane (float4)
constexpr int USEFUL = 120;            // stored cols per warp (lanes 1..30)
constexpr int NSTRIP = 5;              // ceil(512 / 120)
constexpr int SEG = 64;                // output rows per warp task
constexpr int NSEG = H / SEG;          // 8
constexpr int WPB = 4;                 // warps per block
constexpr int NTASK = NPLANE * NSTRIP * NSEG;   // 5120
constexpr int NBLOCK = NTASK / WPB;             // 1280

__global__ void __launch_bounds__(WPB * 32, 5)
guided_filter_kernel(const float* __restrict__ gI,
                     const float* __restrict__ gP,
                     float* __restrict__ gO)
{
    const int lane = threadIdx.x & 31;
    const int task = blockIdx.x * WPB + (threadIdx.x >> 5);

    const int pl  = task / (NSTRIP * NSEG);
    const int rem = task - pl * (NSTRIP * NSEG);
    const int sx  = rem >> 3;          // / NSEG
    const int sy  = rem & 7;

    // Lane owns columns x0 .. x0+3 (4-aligned: fully inside or fully outside)
    const int xb = sx * USEFUL - 4;
    const int x0 = xb + CPL * lane;
    const bool vecok = (x0 >= 0) && (x0 + 3 < W);
    const bool stok  = vecok && (lane >= 1) && (lane <= 30);

    const size_t pbase = (size_t)pl * (size_t)(H * W);
    const float* baseI = gI + pbase;
    const float* baseP = gP + pbase;
    float*       baseO = gO + pbase;

    // Per-column horizontal normalization, cy=3 case: 1/(3*cx), cx in {2,3}.
    // 0 for out-of-image columns -> a=b=0 exactly there (cov=var=0).
    float inv3[CPL];
#pragma unroll
    for (int j = 0; j < CPL; ++j) {
        const int xc = x0 + j;
        const float cx = (xc >= 1 && xc <= W - 2) ? 3.0f : 2.0f;
        inv3[j] = ((unsigned)xc < (unsigned)W) ? 1.0f / (3.0f * cx) : 0.0f;
    }

    const int r0 = sy * SEG;

    // Raw-row rings (vertical-first): slot 2 = newest row y; slot 0 = y-2.
    float rI[3][CPL], rP[3][CPL];
    // Rings of horizontal 1x3 sums of a,b.
    float hA[3][CPL], hB[3][CPL];
#pragma unroll
    for (int k = 0; k < 3; ++k)
#pragma unroll
        for (int j = 0; j < CPL; ++j) {
            rI[k][j] = 0.f; rP[k][j] = 0.f; hA[k][j] = 0.f; hB[k][j] = 0.f;
        }

    // ---- stage 1: load row y into ring slot 2 ----
    auto stage_load = [&](int y) {
#pragma unroll
        for (int j = 0; j < CPL; ++j) {
            rI[0][j] = rI[1][j]; rI[1][j] = rI[2][j];
            rP[0][j] = rP[1][j]; rP[1][j] = rP[2][j];
        }
        float4 Iv = make_float4(0.f, 0.f, 0.f, 0.f);
        float4 Pv = make_float4(0.f, 0.f, 0.f, 0.f);
        if (vecok && (unsigned)y < (unsigned)H) {
            const size_t off = (size_t)y * W + x0;
            Iv = *reinterpret_cast<const float4*>(baseI + off);
            Pv = *reinterpret_cast<const float4*>(baseP + off);
        }
        rI[2][0] = Iv.x; rI[2][1] = Iv.y; rI[2][2] = Iv.z; rI[2][3] = Iv.w;
        rP[2][0] = Pv.x; rP[2][1] = Pv.y; rP[2][2] = Pv.z; rP[2][3] = Pv.w;
    };

    // ---- stage 2: vertical sums over the 3 ring rows, then horizontal 1x3
    //      across columns (via shuffle at lane boundaries) -> a,b -> their
    //      horizontal 1x3 sums into hA/hB slot 2.
    // fy: 0 out-of-image row (a=b=0 exactly), 1.5 at y-edges (cy=2), 1 interior.
    auto stage_ab = [&](int ry) {
        const float fy = ((unsigned)ry < (unsigned)H)
                           ? ((ry == 0 || ry == H - 1) ? 1.5f : 1.0f) : 0.0f;
        float VI[CPL], VP[CPL], VII[CPL], VIP[CPL];
#pragma unroll
        for (int j = 0; j < CPL; ++j) {
            VI[j] = rI[0][j] + rI[1][j] + rI[2][j];
            VP[j] = rP[0][j] + rP[1][j] + rP[2][j];
            VII[j] = fmaf(rI[0][j], rI[0][j],
                      fmaf(rI[1][j], rI[1][j], rI[2][j] * rI[2][j]));
            VIP[j] = fmaf(rI[0][j], rP[0][j],
                      fmaf(rI[1][j], rP[1][j], rI[2][j] * rP[2][j]));
        }
        const float VIl  = __shfl_up_sync(FULL_MASK, VI[3], 1);
        const float VIr  = __shfl_down_sync(FULL_MASK, VI[0], 1);
        const float VPl  = __shfl_up_sync(FULL_MASK, VP[3], 1);
        const float VPr  = __shfl_down_sync(FULL_MASK, VP[0], 1);
        const float VIIl = __shfl_up_sync(FULL_MASK, VII[3], 1);
        const float VIIr = __shfl_down_sync(FULL_MASK, VII[0], 1);
        const float VIPl = __shfl_up_sync(FULL_MASK, VIP[3], 1);
        const float VIPr = __shfl_down_sync(FULL_MASK, VIP[0], 1);

        // Horizontal 1x3 of the vertical sums (pair-sum sharing).
        float SI[CPL], SP[CPL], SII[CPL], SIP[CPL];
        {
            const float s01 = VI[0] + VI[1], s12 = VI[1] + VI[2], s23 = VI[2] + VI[3];
            SI[0] = VIl + s01; SI[1] = s01 + VI[2]; SI[2] = s12 + VI[3]; SI[3] = s23 + VIr;
        }
        {
            const float s01 = VP[0] + VP[1], s12 = VP[1] + VP[2], s23 = VP[2] + VP[3];
            SP[0] = VPl + s01; SP[1] = s01 + VP[2]; SP[2] = s12 + VP[3]; SP[3] = s23 + VPr;
        }
        {
            const float s01 = VII[0] + VII[1], s12 = VII[1] + VII[2], s23 = VII[2] + VII[3];
            SII[0] = VIIl + s01; SII[1] = s01 + VII[2]; SII[2] = s12 + VII[3]; SII[3] = s23 + VIIr;
        }
        {
            const float s01 = VIP[0] + VIP[1], s12 = VIP[1] + VIP[2], s23 = VIP[2] + VIP[3];
            SIP[0] = VIPl + s01; SIP[1] = s01 + VIP[2]; SIP[2] = s12 + VIP[3]; SIP[3] = s23 + VIPr;
        }

        float a[CPL], b[CPL];
#pragma unroll
        for (int j = 0; j < CPL; ++j) {
            const float invc = fy * inv3[j];
            const float mI  = SI[j]  * invc;
            const float mP  = SP[j]  * invc;
            const float mII = SII[j] * invc;
            const float mIP = SIP[j] * invc;
            const float var = fmaf(-mI, mI, mII);
            const float cov = fmaf(-mI, mP, mIP);
            const float av  = __fdividef(cov, var + 0.01f);
            a[j] = av;
            b[j] = fmaf(-av, mI, mP);
        }
        const float al = __shfl_up_sync(FULL_MASK, a[3], 1);
        const float ar = __shfl_down_sync(FULL_MASK, a[0], 1);
        const float bl = __shfl_up_sync(FULL_MASK, b[3], 1);
        const float br = __shfl_down_sync(FULL_MASK, b[0], 1);
#pragma unroll
        for (int j = 0; j < CPL; ++j) {
            hA[0][j] = hA[1][j]; hA[1][j] = hA[2][j];
            hB[0][j] = hB[1][j]; hB[1][j] = hB[2][j];
        }
        const float a01 = a[0] + a[1], a12 = a[1] + a[2], a23 = a[2] + a[3];
        hA[2][0] = al + a01;  hA[2][1] = a01 + a[2];
        hA[2][2] = a12 + a[3]; hA[2][3] = a23 + ar;
        const float b01 = b[0] + b[1], b12 = b[1] + b[2], b23 = b[2] + b[3];
        hB[2][0] = bl + b01;  hB[2][1] = b01 + b[2];
        hB[2][2] = b12 + b[3]; hB[2][3] = b23 + br;
    };

    // ---- stage 3: blur a,b at row ro; raw I at ro sits in ring slot 0 ----
    auto stage_out = [&](int ro) {
        const float fo = (ro == 0 || ro == H - 1) ? 1.5f : 1.0f;
        float o[CPL];
#pragma unroll
        for (int j = 0; j < CPL; ++j) {
            const float invo = fo * inv3[j];
            const float SA = hA[0][j] + hA[1][j] + hA[2][j];
            const float SB = hB[0][j] + hB[1][j] + hB[2][j];
            o[j] = fmaf(SA, rI[0][j], SB) * invo;
        }
        if (stok) {
            *reinterpret_cast<float4*>(baseO + (size_t)ro * W + x0) =
                make_float4(o[0], o[1], o[2], o[3]);
        }
    };

    // Prologue: prime rings on rows r0-2 .. r0+1.
#pragma unroll
    for (int it = 0; it < 4; ++it) {
        const int y = r0 - 2 + it;
        stage_load(y);
        if (it >= 2) stage_ab(y - 1);
    }
    // Steady state: y = r0+2 .. r0+65; out rows r0 .. r0+63.
#pragma unroll 3
    for (int it = 0; it < SEG; ++it) {
        const int y = r0 + 2 + it;
        stage_load(y);
        stage_ab(y - 1);
        stage_out(y - 2);
    }
}

extern "C" void kernel_launch(void* const* d_in, const int* in_sizes, int n_in,
                              void* d_out, int out_size) {
    const float* I = (const float*)d_in[0];   // input
    const float* P = (const float*)d_in[1];   // guide
    float* O = (float*)d_out;
    guided_filter_kernel<<<NBLOCK, WPB * 32>>>(I, P, O);
}

// round 8
// speedup vs baseline: 1.4329x; 1.4329x over previous
#include <cuda_runtime.h>

#define FULL_MASK 0xFFFFFFFFu

constexpr int H = 512;
constexpr int W = 512;
constexpr int NPLANE = 8 * 16;         // 128 independent planes
constexpr int CPL = 4;                 // columns per lane (float4)
constexpr int USEFUL = 120;            // stored cols per warp (lanes 1..30)
constexpr int NSTRIP = 5;              // ceil(512 / 120)
constexpr int SEG = 64;                // output rows per warp task
constexpr int NSEG = H / SEG;          // 8
constexpr int WPB = 4;                 // warps per block
constexpr int NTASK = NPLANE * NSTRIP * NSEG;   // 5120
constexpr int NBLOCK = NTASK / WPB;             // 1280
constexpr int DEPTH = 4;               // cp.async stages (distance-3 prefetch)

__global__ void __launch_bounds__(WPB * 32, 5)
guided_filter_kernel(const float* __restrict__ gI,
                     const float* __restrict__ gP,
                     float* __restrict__ gO)
{
    // Per-warp-private staging: [warp][stage][I/P][lane] -> 16 KB/block.
    __shared__ float4 sbuf[WPB][DEPTH][2][32];

    const int lane = threadIdx.x & 31;
    const int w    = threadIdx.x >> 5;
    const int task = blockIdx.x * WPB + w;

    const int pl  = task / (NSTRIP * NSEG);
    const int rem = task - pl * (NSTRIP * NSEG);
    const int sx  = rem >> 3;          // / NSEG
    const int sy  = rem & 7;

    // Lane owns columns x0..x0+3 (4-aligned: fully inside or fully outside).
    const int xb = sx * USEFUL - 4;
    const int x0 = xb + CPL * lane;
    const bool vecok = (x0 >= 0) && (x0 + 3 < W);
    const bool stok  = vecok && (lane >= 1) && (lane <= 30);
    const int xsafe  = vecok ? x0 : 0;

    const size_t pbase = (size_t)pl * (size_t)(H * W);
    const float* baseI = gI + pbase;
    const float* baseP = gP + pbase;
    float*       baseO = gO + pbase;

    // Per-column horizontal normalization, cy=3 case: 1/(3*cx), cx in {2,3}.
    // 0 for out-of-image columns -> a=b=0 exactly there (cov=var=0).
    float inv3[CPL];
#pragma unroll
    for (int j = 0; j < CPL; ++j) {
        const int xc = x0 + j;
        const float cx = (xc >= 1 && xc <= W - 2) ? 3.0f : 2.0f;
        inv3[j] = ((unsigned)xc < (unsigned)W) ? 1.0f / (3.0f * cx) : 0.0f;
    }

    const int r0 = sy * SEG;

    // Raw-row rings: slot 2 = newest row y; slot 0 = y-2.
    float rI[3][CPL], rP[3][CPL];
    // Rings of horizontal 1x3 sums of a,b.
    float hA[3][CPL], hB[3][CPL];
#pragma unroll
    for (int k = 0; k < 3; ++k)
#pragma unroll
        for (int j = 0; j < CPL; ++j) {
            rI[k][j] = 0.f; rP[k][j] = 0.f; hA[k][j] = 0.f; hB[k][j] = 0.f;
        }

    // ---- async stage: request row y into smem stage s (one commit group) ----
    auto issue_cp = [&](int y, int s) {
        const int yy = y < 0 ? 0 : (y > H - 1 ? H - 1 : y);
        const float* srcI = baseI + (size_t)yy * W + xsafe;
        const float* srcP = baseP + (size_t)yy * W + xsafe;
        const unsigned sz = (vecok && (unsigned)y < (unsigned)H) ? 16u : 0u;
        const unsigned dI = (unsigned)__cvta_generic_to_shared(&sbuf[w][s][0][lane]);
        const unsigned dP = (unsigned)__cvta_generic_to_shared(&sbuf[w][s][1][lane]);
        asm volatile("cp.async.cg.shared.global [%0], [%1], 16, %2;"
                     :: "r"(dI), "l"(srcI), "r"(sz));
        asm volatile("cp.async.cg.shared.global [%0], [%1], 16, %2;"
                     :: "r"(dP), "l"(srcP), "r"(sz));
        asm volatile("cp.async.commit_group;" ::: "memory");
    };

    // ---- consume smem stage s into ring slot 2 (data requested 3 rows ago) ----
    auto stage_consume = [&](int s) {
#pragma unroll
        for (int j = 0; j < CPL; ++j) {
            rI[0][j] = rI[1][j]; rI[1][j] = rI[2][j];
            rP[0][j] = rP[1][j]; rP[1][j] = rP[2][j];
        }
        asm volatile("cp.async.wait_group 3;" ::: "memory");
        const float4 Iv = sbuf[w][s][0][lane];
        const float4 Pv = sbuf[w][s][1][lane];
        rI[2][0] = Iv.x; rI[2][1] = Iv.y; rI[2][2] = Iv.z; rI[2][3] = Iv.w;
        rP[2][0] = Pv.x; rP[2][1] = Pv.y; rP[2][2] = Pv.z; rP[2][3] = Pv.w;
    };

    // ---- vertical sums -> horizontal 1x3 -> a,b -> horizontal 1x3 of a,b ----
    auto stage_ab = [&](int ry) {
        const float fy = ((unsigned)ry < (unsigned)H)
                           ? ((ry == 0 || ry == H - 1) ? 1.5f : 1.0f) : 0.0f;
        float VI[CPL], VP[CPL], VII[CPL], VIP[CPL];
#pragma unroll
        for (int j = 0; j < CPL; ++j) {
            VI[j] = rI[0][j] + rI[1][j] + rI[2][j];
            VP[j] = rP[0][j] + rP[1][j] + rP[2][j];
            VII[j] = fmaf(rI[0][j], rI[0][j],
                      fmaf(rI[1][j], rI[1][j], rI[2][j] * rI[2][j]));
            VIP[j] = fmaf(rI[0][j], rP[0][j],
                      fmaf(rI[1][j], rP[1][j], rI[2][j] * rP[2][j]));
        }
        const float VIl  = __shfl_up_sync(FULL_MASK, VI[3], 1);
        const float VIr  = __shfl_down_sync(FULL_MASK, VI[0], 1);
        const float VPl  = __shfl_up_sync(FULL_MASK, VP[3], 1);
        const float VPr  = __shfl_down_sync(FULL_MASK, VP[0], 1);
        const float VIIl = __shfl_up_sync(FULL_MASK, VII[3], 1);
        const float VIIr = __shfl_down_sync(FULL_MASK, VII[0], 1);
        const float VIPl = __shfl_up_sync(FULL_MASK, VIP[3], 1);
        const float VIPr = __shfl_down_sync(FULL_MASK, VIP[0], 1);

        float SI[CPL], SP[CPL], SII[CPL], SIP[CPL];
        {
            const float s01 = VI[0] + VI[1], s12 = VI[1] + VI[2], s23 = VI[2] + VI[3];
            SI[0] = VIl + s01; SI[1] = s01 + VI[2]; SI[2] = s12 + VI[3]; SI[3] = s23 + VIr;
        }
        {
            const float s01 = VP[0] + VP[1], s12 = VP[1] + VP[2], s23 = VP[2] + VP[3];
            SP[0] = VPl + s01; SP[1] = s01 + VP[2]; SP[2] = s12 + VP[3]; SP[3] = s23 + VPr;
        }
        {
            const float s01 = VII[0] + VII[1], s12 = VII[1] + VII[2], s23 = VII[2] + VII[3];
            SII[0] = VIIl + s01; SII[1] = s01 + VII[2]; SII[2] = s12 + VII[3]; SII[3] = s23 + VIIr;
        }
        {
            const float s01 = VIP[0] + VIP[1], s12 = VIP[1] + VIP[2], s23 = VIP[2] + VIP[3];
            SIP[0] = VIPl + s01; SIP[1] = s01 + VIP[2]; SIP[2] = s12 + VIP[3]; SIP[3] = s23 + VIPr;
        }

        float a[CPL], b[CPL];
#pragma unroll
        for (int j = 0; j < CPL; ++j) {
            const float invc = fy * inv3[j];
            const float mI  = SI[j]  * invc;
            const float mP  = SP[j]  * invc;
            const float mII = SII[j] * invc;
            const float mIP = SIP[j] * invc;
            const float var = fmaf(-mI, mI, mII);
            const float cov = fmaf(-mI, mP, mIP);
            const float av  = __fdividef(cov, var + 0.01f);
            a[j] = av;
            b[j] = fmaf(-av, mI, mP);
        }
        const float al = __shfl_up_sync(FULL_MASK, a[3], 1);
        const float ar = __shfl_down_sync(FULL_MASK, a[0], 1);
        const float bl = __shfl_up_sync(FULL_MASK, b[3], 1);
        const float br = __shfl_down_sync(FULL_MASK, b[0], 1);
#pragma unroll
        for (int j = 0; j < CPL; ++j) {
            hA[0][j] = hA[1][j]; hA[1][j] = hA[2][j];
            hB[0][j] = hB[1][j]; hB[1][j] = hB[2][j];
        }
        const float a01 = a[0] + a[1], a12 = a[1] + a[2], a23 = a[2] + a[3];
        hA[2][0] = al + a01;  hA[2][1] = a01 + a[2];
        hA[2][2] = a12 + a[3]; hA[2][3] = a23 + ar;
        const float b01 = b[0] + b[1], b12 = b[1] + b[2], b23 = b[2] + b[3];
        hB[2][0] = bl + b01;  hB[2][1] = b01 + b[2];
        hB[2][2] = b12 + b[3]; hB[2][3] = b23 + br;
    };

    // ---- blur a,b at row ro; raw I at ro sits in ring slot 0 ----
    auto stage_out = [&](int ro) {
        const float fo = (ro == 0 || ro == H - 1) ? 1.5f : 1.0f;
        float o[CPL];
#pragma unroll
        for (int j = 0; j < CPL; ++j) {
            const float invo = fo * inv3[j];
            const float SA = hA[0][j] + hA[1][j] + hA[2][j];
            const float SB = hB[0][j] + hB[1][j] + hB[2][j];
            o[j] = fmaf(SA, rI[0][j], SB) * invo;
        }
        if (stok) {
            *reinterpret_cast<float4*>(baseO + (size_t)ro * W + x0) =
                make_float4(o[0], o[1], o[2], o[3]);
        }
    };

    // ---- pipeline ----
    // Pre-issue rows r0-2 .. r0 into stages 0..2 (3 groups in flight).
#pragma unroll
    for (int k = 0; k < DEPTH - 1; ++k)
        issue_cp(r0 - 2 + k, k);

    // Unified loop over 68 consumed rows; unroll 4 makes stage index constant.
#pragma unroll 4
    for (int t = 0; t < SEG + 4; ++t) {
        const int y = r0 - 2 + t;
        issue_cp(y + 3, (t + 3) & (DEPTH - 1));   // 4 groups in flight
        stage_consume(t & (DEPTH - 1));           // wait_group 3 -> row y ready
        if (t >= 2) stage_ab(y - 1);
        if (t >= 4) stage_out(y - 2);
    }
}

extern "C" void kernel_launch(void* const* d_in, const int* in_sizes, int n_in,
                              void* d_out, int out_size) {
    const float* I = (const float*)d_in[0];   // input
    const float* P = (const float*)d_in[1];   // guide
    float* O = (float*)d_out;
    guided_filter_kernel<<<NBLOCK, WPB * 32>>>(I, P, O);
}